// round 6
// baseline (speedup 1.0000x reference)
#include <cuda_runtime.h>
#include <math.h>

#define NE    14
#define NSV   256
#define NPVs  33
#define NPAIR 196
#define NORB  112
#define NFB   3

struct __align__(16) Smem {
    float sv[2][NE][NSV];        // 28672 B
    float pv[2][NPAIR * NPVs];   // 51744 B (reused as orbm swizzled)
    float red[4][2][NE][NSV];    // 114688 B: k-split partials, plain stores
    float scr[2][896];
    float mumd[2][512];
    float cm[2][NSV];
    float sin8[2][NE][8];
    float env[2][NE];
    float rl[2][NE][3];
    float ldet[2][32];
    float sgn[2][32];
};

union U64 { unsigned long long u; float2 f; };

__device__ __forceinline__ void ffma2(unsigned long long &d, unsigned long long a, unsigned long long b) {
    asm("fma.rn.f32x2 %0, %1, %2, %0;" : "+l"(d) : "l"(a), "l"(b));
}
__device__ __forceinline__ unsigned long long dup2(float x) {
    unsigned long long r;
    asm("mov.b64 %0, {%1, %1};" : "=l"(r) : "f"(x));
    return r;
}
__device__ __forceinline__ int swz(int c)  { return c ^ (c >> 5); }
__device__ __forceinline__ int swzo(int o) { return o ^ (o >> 5); }

__device__ __forceinline__ float fast_tanh(float x) {
    float e = __expf(2.0f * x);
    return 1.0f - __fdividef(2.0f, e + 1.0f);
}

__global__ void __launch_bounds__(1024, 1)
ansatz_kernel(const float* __restrict__ r,
              const float* __restrict__ s_w0, const float* __restrict__ s_b0,
              const float* __restrict__ s_w,  const float* __restrict__ s_b,
              const float* __restrict__ p_w0, const float* __restrict__ p_b0,
              const float* __restrict__ p_w,  const float* __restrict__ p_b,
              const float* __restrict__ va_w, const float* __restrict__ va_b,
              const float* __restrict__ wu_w, const float* __restrict__ wu_b,
              const float* __restrict__ wd_w, const float* __restrict__ wd_b,
              const float* __restrict__ wf_w,
              float* __restrict__ out, int nb)
{
    extern __shared__ char smem_raw[];
    Smem& s = *reinterpret_cast<Smem*>(smem_raw);

    const int t    = threadIdx.x;
    const int lane = t & 31;
    const int wid  = t >> 5;          // 0..31
    const int b0   = blockIdx.x * 2;
    const float inv7 = 1.0f / 7.0f;

    const int tc   = t & 255;
    const int tel  = (t >> 8) & 1;    // element for 2x256 views
    const int thalf= t >> 9;          // electron half for 1024-thread views

    // ---------------- Phase 0: geometry ----------------
    for (int q = t; q < 2 * NE * 3; q += 1024) {
        int el = q / (NE * 3);
        int bel = b0 + el; if (bel >= nb) bel = nb - 1;
        ((float*)s.rl[el])[q - el * (NE * 3)] = r[bel * (NE * 3) + (q - el * (NE * 3))];
    }
    __syncthreads();

    if (t < 2 * NE) {
        int el = t / NE, e = t - el * NE;
        float x = s.rl[el][e][0], y = s.rl[el][e][1], z = s.rl[el][e][2];
        float ev = 0.f;
        #pragma unroll
        for (int a = 0; a < 2; ++a) {
            float dz = z - (a ? 1.4f : 0.0f);
            float len = sqrtf(x * x + y * y + dz * dz);
            s.sin8[el][e][a * 4 + 0] = x;
            s.sin8[el][e][a * 4 + 1] = y;
            s.sin8[el][e][a * 4 + 2] = dz;
            s.sin8[el][e][a * 4 + 3] = len;
            ev += __expf(-len);
        }
        s.env[el][e] = ev;
    }
    if (t < 2 * NPAIR) {
        int el = t / NPAIR, pr = t - el * NPAIR;
        int i = pr / 14, j = pr - i * 14;
        float dx = s.rl[el][j][0] - s.rl[el][i][0];
        float dy = s.rl[el][j][1] - s.rl[el][i][1];
        float dz = s.rl[el][j][2] - s.rl[el][i][2];
        float ax = dx, ay = dy, az = dz;
        if (i == j) { ax += 1.f; ay += 1.f; az += 1.f; }
        float len = sqrtf(ax * ax + ay * ay + az * az);
        s.scr[el][pr * 4 + 0] = dx; s.scr[el][pr * 4 + 1] = dy;
        s.scr[el][pr * 4 + 2] = dz; s.scr[el][pr * 4 + 3] = len;
    }
    __syncthreads();

    // layer-0 means
    if (t < 32) {
        int el = t >> 4, q = t & 15;
        int k = q & 7, half = q >> 3;
        float su = 0.f;
        #pragma unroll
        for (int e = 0; e < 7; ++e) su += s.sin8[el][half * 7 + e][k];
        s.mumd[el][half * 8 + k] = su * inv7;
    }
    if (t >= 64 && t < 64 + 224) {
        int q2 = t - 64;
        int el = q2 / 112, q = q2 - el * 112;
        int dn = (q >= 56) ? 1 : 0;
        int qq = q - dn * 56;
        int e = qq >> 2, k = qq & 3;
        int i0 = dn ? 7 : 0;
        float su = 0.f;
        #pragma unroll
        for (int ii = 0; ii < 7; ++ii) su += s.scr[el][((i0 + ii) * 14 + e) * 4 + k];
        s.scr[el][784 + dn * 56 + e * 4 + k] = su * inv7;
    }
    __syncthreads();

    // ---------------- Layer 0 ----------------
    {
        float pnew[32];
        const bool prow = (t < 2 * NPAIR);
        int pel = 0, pr = 0;
        if (prow) {
            pel = t / NPAIR; pr = t - pel * NPAIR;
            const float* pin = s.scr[pel] + pr * 4;
            float r0 = pin[0], r1 = pin[1], r2 = pin[2], r3 = pin[3];
            #pragma unroll
            for (int c2 = 0; c2 < 32; ++c2) {
                float v = p_b0[c2]
                        + r0 * p_w0[0 * 32 + c2] + r1 * p_w0[1 * 32 + c2]
                        + r2 * p_w0[2 * 32 + c2] + r3 * p_w0[3 * 32 + c2];
                pnew[c2] = fast_tanh(v);
            }
        }
        if (t < 512) {
            float cm0 = s_b0[tc];
            #pragma unroll
            for (int k = 0; k < 8; ++k)
                cm0 += s.mumd[tel][k] * s_w0[(8 + k) * 256 + tc] + s.mumd[tel][8 + k] * s_w0[(16 + k) * 256 + tc];
            float acc[NE];
            #pragma unroll
            for (int e = 0; e < NE; ++e) acc[e] = cm0;
            #pragma unroll
            for (int k = 0; k < 8; ++k) {
                float w = s_w0[k * 256 + tc];
                #pragma unroll
                for (int e = 0; e < NE; ++e) acc[e] += s.sin8[tel][e][k] * w;
            }
            const float* pu0 = s.scr[tel] + 784;
            const float* pd0 = s.scr[tel] + 840;
            #pragma unroll
            for (int k = 0; k < 4; ++k) {
                float wuv = s_w0[(24 + k) * 256 + tc];
                float wdv = s_w0[(28 + k) * 256 + tc];
                #pragma unroll
                for (int e = 0; e < NE; ++e)
                    acc[e] += pu0[e * 4 + k] * wuv + pd0[e * 4 + k] * wdv;
            }
            #pragma unroll
            for (int e = 0; e < NE; ++e) s.sv[tel][e][tc] = fast_tanh(acc[e]);
        }
        if (prow) {
            #pragma unroll
            for (int c2 = 0; c2 < 32; ++c2) s.pv[pel][pr * NPVs + c2] = pnew[c2];
        }
    }
    __syncthreads();

    // ---------------- FB layers + final va ----------------
    for (int il = 0; il <= NFB; ++il) {
        const bool last = (il == NFB);
        const float* WL = last ? va_w : (s_w + il * (832 * 256));
        const float* bL = last ? va_b : (s_b + il * 256);
        const float* PW = p_w + il * (32 * 32);
        const float* Pb = p_b + il * 32;

        // (a) means (1024 threads: el x half x 256c) + cm init
        {
            float ssum = 0.f;
            #pragma unroll
            for (int e = 0; e < 7; ++e) ssum += s.sv[tel][thalf * 7 + e][tc];
            s.mumd[tel][thalf * 256 + tc] = ssum * inv7;
        }
        if (t < 512) s.cm[tel][swz(tc)] = bL[tc];
        for (int idx = t; idx < 2 * 896; idx += 1024) {
            int el = idx / 896, q2 = idx - el * 896;
            int dn = (q2 >= 448) ? 1 : 0;
            int q = q2 - dn * 448;
            int e = q >> 5, k = q & 31;
            int i0 = dn ? 7 : 0;
            float su = 0.f;
            #pragma unroll
            for (int ii = 0; ii < 7; ++ii) su += s.pv[el][((i0 + ii) * 14 + e) * NPVs + k];
            s.scr[el][q2] = su * inv7;
        }
        __syncthreads();

        // (b) pair GEMM
        if (!last && t < 2 * NPAIR) {
            int el = t / NPAIR, pr = t - el * NPAIR;
            float row[32];
            #pragma unroll
            for (int k = 0; k < 32; ++k) row[k] = s.pv[el][pr * NPVs + k];
            unsigned long long o[16];
            const ulonglong2* pb2 = (const ulonglong2*)Pb;
            #pragma unroll
            for (int q = 0; q < 8; ++q) {
                ulonglong2 bv = pb2[q];
                o[2 * q] = bv.x; o[2 * q + 1] = bv.y;
            }
            #pragma unroll
            for (int k = 0; k < 32; ++k) {
                unsigned long long rk = dup2(row[k]);
                const ulonglong2* w2 = (const ulonglong2*)(PW + k * 32);
                #pragma unroll
                for (int q = 0; q < 8; ++q) {
                    ulonglong2 wv = w2[q];
                    ffma2(o[2 * q], rk, wv.x);
                    ffma2(o[2 * q + 1], rk, wv.y);
                }
            }
            #pragma unroll
            for (int q = 0; q < 16; ++q) {
                U64 u; u.u = o[q];
                s.pv[el][pr * NPVs + 2 * q]     = fast_tanh(u.f.x) + row[2 * q];
                s.pv[el][pr * NPVs + 2 * q + 1] = fast_tanh(u.f.y) + row[2 * q + 1];
            }
        }

        // (c) cm rank-1: warp wid handles rows [wid*16, wid*16+16), both elems
        {
            const int kb2 = wid * 16;
            const int c0m = lane * 8;
            unsigned long long ca[2][4];
            #pragma unroll
            for (int el = 0; el < 2; ++el)
                #pragma unroll
                for (int p = 0; p < 4; ++p) ca[el][p] = 0ull;
            for (int k = kb2; k < kb2 + 16; ++k) {
                const float* wp = WL + (256 + k) * 256 + c0m;
                ulonglong2 wA = *(const ulonglong2*)(wp);
                ulonglong2 wB = *(const ulonglong2*)(wp + 4);
                #pragma unroll
                for (int el = 0; el < 2; ++el) {
                    unsigned long long d = dup2(s.mumd[el][k]);
                    ffma2(ca[el][0], d, wA.x); ffma2(ca[el][1], d, wA.y);
                    ffma2(ca[el][2], d, wB.x); ffma2(ca[el][3], d, wB.y);
                }
            }
            #pragma unroll
            for (int el = 0; el < 2; ++el)
                #pragma unroll
                for (int p = 0; p < 4; ++p) {
                    U64 u; u.u = ca[el][p];
                    atomicAdd(&s.cm[el][swz(c0m + 2 * p)],     u.f.x);
                    atomicAdd(&s.cm[el][swz(c0m + 2 * p + 1)], u.f.y);
                }
        }

        // (d) main electron GEMM: 32 warps = eh(2) x ch(4) x kh(4); lane = 2 cols
        {
            const int kh  = wid & 3;
            const int ch  = (wid >> 2) & 3;
            const int eh2 = (wid >> 4) & 1;
            const int e0  = eh2 * 7;
            const int c0  = ch * 64 + lane * 2;
            unsigned long long acc[2][7];
            #pragma unroll
            for (int el = 0; el < 2; ++el)
                #pragma unroll
                for (int i = 0; i < 7; ++i) acc[el][i] = 0ull;

            const int kb = kh * 64;
            for (int kk = 0; kk < 64; kk += 4) {
                const int k = kb + kk;
                const float* wp = WL + k * 256 + c0;
                unsigned long long w0 = *(const unsigned long long*)(wp);
                unsigned long long w1 = *(const unsigned long long*)(wp + 256);
                unsigned long long w2 = *(const unsigned long long*)(wp + 512);
                unsigned long long w3 = *(const unsigned long long*)(wp + 768);
                #pragma unroll
                for (int i = 0; i < 7; ++i) {
                    float4 a0 = *(const float4*)&s.sv[0][e0 + i][k];
                    float4 a1 = *(const float4*)&s.sv[1][e0 + i][k];
                    ffma2(acc[0][i], dup2(a0.x), w0);
                    ffma2(acc[0][i], dup2(a0.y), w1);
                    ffma2(acc[0][i], dup2(a0.z), w2);
                    ffma2(acc[0][i], dup2(a0.w), w3);
                    ffma2(acc[1][i], dup2(a1.x), w0);
                    ffma2(acc[1][i], dup2(a1.y), w1);
                    ffma2(acc[1][i], dup2(a1.z), w2);
                    ffma2(acc[1][i], dup2(a1.w), w3);
                }
            }
            // pu/pd extension rows: kh handles k in [kh*8, kh*8+8)
            #pragma unroll
            for (int blk = 0; blk < 2; ++blk) {
                const int rowb = 768 + blk * 32;
                const int scrb = blk * 448;
                #pragma unroll
                for (int kk = 0; kk < 8; kk += 4) {
                    const int k = kh * 8 + kk;
                    const float* wp = WL + (rowb + k) * 256 + c0;
                    unsigned long long w0 = *(const unsigned long long*)(wp);
                    unsigned long long w1 = *(const unsigned long long*)(wp + 256);
                    unsigned long long w2 = *(const unsigned long long*)(wp + 512);
                    unsigned long long w3 = *(const unsigned long long*)(wp + 768);
                    #pragma unroll
                    for (int i = 0; i < 7; ++i) {
                        float4 a0 = *(const float4*)&s.scr[0][scrb + (e0 + i) * 32 + k];
                        float4 a1 = *(const float4*)&s.scr[1][scrb + (e0 + i) * 32 + k];
                        ffma2(acc[0][i], dup2(a0.x), w0);
                        ffma2(acc[0][i], dup2(a0.y), w1);
                        ffma2(acc[0][i], dup2(a0.z), w2);
                        ffma2(acc[0][i], dup2(a0.w), w3);
                        ffma2(acc[1][i], dup2(a1.x), w0);
                        ffma2(acc[1][i], dup2(a1.y), w1);
                        ffma2(acc[1][i], dup2(a1.z), w2);
                        ffma2(acc[1][i], dup2(a1.w), w3);
                    }
                }
            }
            // plain STS.64 partials: warp owns (kh, el, e, c) tile
            #pragma unroll
            for (int el = 0; el < 2; ++el)
                #pragma unroll
                for (int i = 0; i < 7; ++i) {
                    U64 u; u.u = acc[el][i];
                    *reinterpret_cast<float2*>(&s.red[kh][el][e0 + i][c0]) = u.f;
                }
        }
        __syncthreads();

        // (e) epilogue: 1024 threads = el x half x 256c, 7 e each
        {
            const float cmv = s.cm[tel][swz(tc)];
            #pragma unroll
            for (int ee = 0; ee < 7; ++ee) {
                const int e = thalf * 7 + ee;
                float v = cmv + s.red[0][tel][e][tc] + s.red[1][tel][e][tc]
                              + s.red[2][tel][e][tc] + s.red[3][tel][e][tc];
                v = fast_tanh(v);
                s.sv[tel][e][tc] = last ? v : (v + s.sv[tel][e][tc]);
            }
        }
        __syncthreads();
    }

    // ---------------- Orbitals ----------------
    for (int idx = t; idx < 2 * NE * NORB; idx += 1024) {
        int el = idx / (NE * NORB), q = idx - el * (NE * NORB);
        int e = q / NORB, o = q - e * NORB;
        s.pv[el][e * NORB + swzo(o)] = (e < 7) ? wu_b[o] : wd_b[o];
    }
    __syncthreads();
    {
        const int kh8 = wid & 7;            // 8-way k split, 32 k each
        const int eh2 = (wid >> 3) & 1;
        const int oel = (wid >> 4) & 1;
        const int e0  = eh2 * 7;
        const int oc0 = lane * 4;
        if (oc0 < NORB) {
            const float* W = eh2 ? wd_w : wu_w;
            unsigned long long oa[7][2];
            #pragma unroll
            for (int i = 0; i < 7; ++i) { oa[i][0] = 0ull; oa[i][1] = 0ull; }
            const int kb = kh8 * 32;
            for (int kk = 0; kk < 32; kk += 4) {
                const int k = kb + kk;
                ulonglong2 w0 = *(const ulonglong2*)(W + (k + 0) * NORB + oc0);
                ulonglong2 w1 = *(const ulonglong2*)(W + (k + 1) * NORB + oc0);
                ulonglong2 w2 = *(const ulonglong2*)(W + (k + 2) * NORB + oc0);
                ulonglong2 w3 = *(const ulonglong2*)(W + (k + 3) * NORB + oc0);
                #pragma unroll
                for (int i = 0; i < 7; ++i) {
                    float4 a = *(const float4*)&s.sv[oel][e0 + i][k];
                    ffma2(oa[i][0], dup2(a.x), w0.x); ffma2(oa[i][1], dup2(a.x), w0.y);
                    ffma2(oa[i][0], dup2(a.y), w1.x); ffma2(oa[i][1], dup2(a.y), w1.y);
                    ffma2(oa[i][0], dup2(a.z), w2.x); ffma2(oa[i][1], dup2(a.z), w2.y);
                    ffma2(oa[i][0], dup2(a.w), w3.x); ffma2(oa[i][1], dup2(a.w), w3.y);
                }
            }
            #pragma unroll
            for (int i = 0; i < 7; ++i)
                #pragma unroll
                for (int p = 0; p < 2; ++p) {
                    U64 u; u.u = oa[i][p];
                    int o0 = oc0 + 2 * p;
                    atomicAdd(&s.pv[oel][(e0 + i) * NORB + swzo(o0)],     u.f.x);
                    atomicAdd(&s.pv[oel][(e0 + i) * NORB + swzo(o0 + 1)], u.f.y);
                }
        }
    }
    __syncthreads();
    for (int idx = t; idx < 2 * NE * NORB; idx += 1024) {
        int el = idx / (NE * NORB), q = idx - el * (NE * NORB);
        int e = q / NORB;
        s.pv[el][q] *= s.env[el][e];
    }
    __syncthreads();

    // ---------------- 2 x 32 slogdets of 7x7 ----------------
    if (t < 64) {
        const int el = t >> 5, tt = t & 31;
        const int sp = tt >> 4, d = tt & 15;
        float m[7][7];
        #pragma unroll
        for (int j = 0; j < 7; ++j) {
            int og = swzo(j * 16 + d);
            #pragma unroll
            for (int i = 0; i < 7; ++i)
                m[j][i] = s.pv[el][(sp * 7 + i) * NORB + og];
        }
        float ld = 0.f, sg = 1.f;
        #pragma unroll
        for (int col = 0; col < 7; ++col) {
            #pragma unroll
            for (int rr = col + 1; rr < 7; ++rr) {
                if (fabsf(m[rr][col]) > fabsf(m[col][col])) {
                    sg = -sg;
                    #pragma unroll
                    for (int cc = 0; cc < 7; ++cc) {
                        float tmp = m[col][cc]; m[col][cc] = m[rr][cc]; m[rr][cc] = tmp;
                    }
                }
            }
            float piv = m[col][col];
            sg = (piv < 0.f) ? -sg : sg;
            ld += __logf(fabsf(piv));
            float inv = 1.f / piv;
            #pragma unroll
            for (int rr = col + 1; rr < 7; ++rr) {
                float f = m[rr][col] * inv;
                #pragma unroll
                for (int cc = col + 1; cc < 7; ++cc)
                    m[rr][cc] -= f * m[col][cc];
            }
        }
        s.ldet[el][tt] = ld;
        s.sgn[el][tt] = sg;
    }
    __syncthreads();

    if (t < 2 && (b0 + t) < nb) {
        const int el = t;
        float l[16], mx = -3.4e38f;
        #pragma unroll
        for (int d = 0; d < 16; ++d) {
            l[d] = s.ldet[el][d] + s.ldet[el][16 + d];
            mx = fmaxf(mx, l[d]);
        }
        float psi = 0.f;
        #pragma unroll
        for (int d = 0; d < 16; ++d)
            psi += s.sgn[el][d] * s.sgn[el][16 + d] * __expf(l[d] - mx) * wf_w[d];
        out[b0 + el] = __logf(fabsf(psi)) + mx;
    }
}

extern "C" void kernel_launch(void* const* d_in, const int* in_sizes, int n_in,
                              void* d_out, int out_size)
{
    const float* r    = (const float*)d_in[0];
    const float* s_w0 = (const float*)d_in[1];
    const float* s_b0 = (const float*)d_in[2];
    const float* s_w  = (const float*)d_in[3];
    const float* s_b  = (const float*)d_in[4];
    const float* p_w0 = (const float*)d_in[5];
    const float* p_b0 = (const float*)d_in[6];
    const float* p_w  = (const float*)d_in[7];
    const float* p_b  = (const float*)d_in[8];
    const float* va_w = (const float*)d_in[9];
    const float* va_b = (const float*)d_in[10];
    const float* wu_w = (const float*)d_in[11];
    const float* wu_b = (const float*)d_in[12];
    const float* wd_w = (const float*)d_in[13];
    const float* wd_b = (const float*)d_in[14];
    const float* wf_w = (const float*)d_in[15];

    const int nb  = in_sizes[0] / (14 * 3);
    const int nb2 = (nb + 1) / 2;
    const int smem = (int)sizeof(Smem);
    cudaFuncSetAttribute(ansatz_kernel, cudaFuncAttributeMaxDynamicSharedMemorySize, smem);
    ansatz_kernel<<<nb2, 1024, smem>>>(r, s_w0, s_b0, s_w, s_b, p_w0, p_b0, p_w, p_b,
                                       va_w, va_b, wu_w, wu_b, wd_w, wd_b, wf_w,
                                       (float*)d_out, nb);
}